// round 6
// baseline (speedup 1.0000x reference)
#include <cuda_runtime.h>

// Performer / FAVOR+ attention, fp32, GB300 sm_103a.
// Round 5: occupancy push. Kernel A: CHUNK=32 -> 113KB smem -> 2 CTAs/SM.
// Kernel B: 512 threads (16 warps) + transposed-kv GEMM3 (all-packed FFMA2).
// Reduce: float4-vectorized.

#define BHN    32
#define NSEQ   4096
#define DDIM   64
#define FDIM   256
#define NSPLIT 32
#define RPB    (NSEQ / NSPLIT)   // 128 rows per block

// Kernel A tiling
#define TBLKA  256
#define CHKA   32
#define NCHA   (RPB / CHKA)      // 4
#define XPADA  36
// Kernel B tiling
#define TBLKB  512
#define CHKB   64
#define NCHB   (RPB / CHKB)      // 2
#define XPADB  68
#define KVP    260               // padded KVT row stride (floats)

typedef unsigned long long u64;

// Static device scratch (allocation-free contract).
__device__ float g_part_kv[(size_t)BHN * NSPLIT * FDIM * DDIM]; // 67 MB
__device__ float g_part_ks[(size_t)BHN * NSPLIT * FDIM];
__device__ float g_kv[(size_t)BHN * FDIM * DDIM];
__device__ float g_ks[(size_t)BHN * FDIM];

// ---------------- packed f32x2 helpers ----------------
__device__ __forceinline__ u64 pk2(float lo, float hi) {
    u64 r; asm("mov.b64 %0, {%1,%2};" : "=l"(r) : "f"(lo), "f"(hi)); return r;
}
__device__ __forceinline__ u64 dup2(float x) { return pk2(x, x); }
__device__ __forceinline__ void upk2(float& lo, float& hi, u64 v) {
    asm("mov.b64 {%0,%1}, %2;" : "=f"(lo), "=f"(hi) : "l"(v));
}
__device__ __forceinline__ void ffma2(u64& d, u64 a, u64 b) {
    asm("fma.rn.f32x2 %0, %1, %2, %0;" : "+l"(d) : "l"(a), "l"(b));
}
__device__ __forceinline__ void fadd2(u64& d, u64 a) {
    asm("add.rn.f32x2 %0, %1, %2;" : "=l"(d) : "l"(d), "l"(a));
}

// ---------------------------------------------------------------------------
// GEMM1 (4-row tile, col-pair packed): S[rows][256] = X[rows][64] @ P[64][256].
// Thread (rg, cg=lane) owns rows rg*4..rg*4+3, cols {cg*4+j, 128+cg*4+j}.
// accp[i][hc][jp] lanes = cols (hc*128+cg*4+2jp, +1): b-pairs free from
// ulonglong2 reinterp of Ps float4 rows; a scalars duplicated (4 MOV/d).
// ---------------------------------------------------------------------------
__device__ __forceinline__ void proj_gemm4(const float* __restrict__ XsT,
                                           const float* __restrict__ Ps,
                                           int rg, int cg, int xpad,
                                           u64 accp[4][2][2])
{
#pragma unroll
    for (int i = 0; i < 4; i++)
#pragma unroll
        for (int hc = 0; hc < 2; hc++)
#pragma unroll
            for (int jp = 0; jp < 2; jp++) accp[i][hc][jp] = 0ull;

#pragma unroll 4
    for (int d = 0; d < DDIM; d++) {
        float4 A = *(const float4*)(XsT + d * xpad + rg * 4);   // warp-broadcast
        u64 ad[4] = {dup2(A.x), dup2(A.y), dup2(A.z), dup2(A.w)};
        ulonglong2 B0 = *(const ulonglong2*)(Ps + d * FDIM + cg * 4);
        ulonglong2 B1 = *(const ulonglong2*)(Ps + d * FDIM + 128 + cg * 4);
        u64 bp[2][2] = {{B0.x, B0.y}, {B1.x, B1.y}};
#pragma unroll
        for (int i = 0; i < 4; i++)
#pragma unroll
            for (int hc = 0; hc < 2; hc++)
#pragma unroll
                for (int jp = 0; jp < 2; jp++)
                    ffma2(accp[i][hc][jp], ad[i], bp[hc][jp]);
    }
}

__device__ __forceinline__ void unpack4(const u64 accp[4][2][2], float acc[4][2][4])
{
#pragma unroll
    for (int i = 0; i < 4; i++)
#pragma unroll
        for (int hc = 0; hc < 2; hc++)
#pragma unroll
            for (int jp = 0; jp < 2; jp++)
                upk2(acc[i][hc][2 * jp], acc[i][hc][2 * jp + 1], accp[i][hc][jp]);
}

// Row-max across warp (row's 256 cols span the 32 lanes), then exp * 1/16.
__device__ __forceinline__ void maxexp4(float acc[4][2][4])
{
#pragma unroll
    for (int i = 0; i < 4; i++) {
        float m = acc[i][0][0];
#pragma unroll
        for (int hc = 0; hc < 2; hc++)
#pragma unroll
            for (int j = 0; j < 4; j++) m = fmaxf(m, acc[i][hc][j]);
#pragma unroll
        for (int off = 16; off > 0; off >>= 1)
            m = fmaxf(m, __shfl_xor_sync(0xffffffffu, m, off));
#pragma unroll
        for (int hc = 0; hc < 2; hc++)
#pragma unroll
            for (int j = 0; j < 4; j++)
                acc[i][hc][j] = __expf(acc[i][hc][j] - m) * 0.0625f; // 1/sqrt(256)
    }
}

__device__ __forceinline__ void store_E4(float* __restrict__ Es, int rg, int cg,
                                         const float acc[4][2][4])
{
#pragma unroll
    for (int i = 0; i < 4; i++) {
        int r = rg * 4 + i;
#pragma unroll
        for (int hc = 0; hc < 2; hc++)
            *(float4*)(Es + r * FDIM + hc * 128 + cg * 4) =
                make_float4(acc[i][hc][0], acc[i][hc][1], acc[i][hc][2], acc[i][hc][3]);
    }
}

// ---------------------------------------------------------------------------
// Kernel A: k-side. 256 thr, 2 CTAs/SM.
// smem = P(64K) + XsT 64x36 (9K) + E 32x256 (32K) + V 32x64 (8K) = 115712 B
// ---------------------------------------------------------------------------
__global__ __launch_bounds__(TBLKA, 2)
void favor_k_kernel(const float* __restrict__ K, const float* __restrict__ V,
                    const float* __restrict__ P)
{
    extern __shared__ float sm[];
    float* Ps  = sm;                       // [64][256]
    float* XsT = Ps + DDIM * FDIM;         // [64][XPADA]
    float* Es  = XsT + DDIM * XPADA;       // [32][256]
    float* Vs  = Es + CHKA * FDIM;         // [32][64]

    const int tid = threadIdx.x;
    const int split = blockIdx.x, bh = blockIdx.y;
    const float* kb = K + (size_t)bh * NSEQ * DDIM;
    const float* vb = V + (size_t)bh * NSEQ * DDIM;

    {
        const float4* src = (const float4*)P;
        float4* dst = (float4*)Ps;
#pragma unroll
        for (int it = 0; it < (DDIM * FDIM / 4) / TBLKA; it++)
            dst[tid + it * TBLKA] = src[tid + it * TBLKA];
    }

    const int rg = tid >> 5, cg = tid & 31;   // GEMM1: rows rg*4..+3 (rg 0..7 -> 32 rows)
    const int fg = tid >> 3, dg = tid & 7;    // GEMM2 mapping

    // GEMM2 packed accumulators: kvp[hf][i2][j] lanes = f pair
    // (hf*128+fg*4+2*i2, +1); cols d = hd*32+dg*4+j.
    u64 kvp[2][2][2][4];
    u64 ksp[2][2];
#pragma unroll
    for (int hf = 0; hf < 2; hf++)
#pragma unroll
        for (int i2 = 0; i2 < 2; i2++) {
            ksp[hf][i2] = 0ull;
#pragma unroll
            for (int hd = 0; hd < 2; hd++)
#pragma unroll
                for (int j = 0; j < 4; j++) kvp[hf][i2][hd][j] = 0ull;
        }

    for (int c = 0; c < NCHA; c++) {
        const int n0 = split * RPB + c * CHKA;
        __syncthreads();
        // K chunk transposed: 32x64 elems
#pragma unroll
        for (int it = 0; it < (CHKA * DDIM) / TBLKA; it++) {
            int idx = tid + it * TBLKA;
            int r = idx >> 6, d = idx & 63;
            XsT[d * XPADA + r] = kb[(size_t)(n0 + r) * DDIM + d];
        }
        {   // V chunk: contiguous copy
            const float4* src = (const float4*)(vb + (size_t)n0 * DDIM);
            float4* dst = (float4*)Vs;
#pragma unroll
            for (int it = 0; it < (CHKA * DDIM / 4) / TBLKA; it++)
                dst[tid + it * TBLKA] = src[tid + it * TBLKA];
        }
        __syncthreads();

        u64 accp[4][2][2];
        proj_gemm4(XsT, Ps, rg, cg, XPADA, accp);
        float acc[4][2][4];
        unpack4(accp, acc);
        maxexp4(acc);
        store_E4(Es, rg, cg, acc);
        __syncthreads();

        // GEMM2 (packed): kv[f][d] += sum_r E[r][f]*V[r][d]; ksum[f] += E[r][f]
#pragma unroll 4
        for (int r = 0; r < CHKA; r++) {
            ulonglong2 A0 = *(const ulonglong2*)(Es + r * FDIM + fg * 4);
            ulonglong2 A1 = *(const ulonglong2*)(Es + r * FDIM + 128 + fg * 4);
            u64 ap[2][2] = {{A0.x, A0.y}, {A1.x, A1.y}};
            float4 V0 = *(const float4*)(Vs + r * DDIM + dg * 4);
            float4 V1 = *(const float4*)(Vs + r * DDIM + 32 + dg * 4);
            u64 bd[2][4] = {{dup2(V0.x), dup2(V0.y), dup2(V0.z), dup2(V0.w)},
                            {dup2(V1.x), dup2(V1.y), dup2(V1.z), dup2(V1.w)}};
#pragma unroll
            for (int hf = 0; hf < 2; hf++)
#pragma unroll
                for (int i2 = 0; i2 < 2; i2++) {
                    fadd2(ksp[hf][i2], ap[hf][i2]);
#pragma unroll
                    for (int hd = 0; hd < 2; hd++)
#pragma unroll
                        for (int j = 0; j < 4; j++)
                            ffma2(kvp[hf][i2][hd][j], ap[hf][i2], bd[hd][j]);
                }
        }
    }

    // Write per-split partials (no atomics -> deterministic)
    float* pkv = g_part_kv + ((size_t)(bh * NSPLIT + split)) * FDIM * DDIM;
    float* pks = g_part_ks + (size_t)(bh * NSPLIT + split) * FDIM;
#pragma unroll
    for (int hf = 0; hf < 2; hf++)
#pragma unroll
        for (int i2 = 0; i2 < 2; i2++) {
            float rowlo[2][4], rowhi[2][4];
#pragma unroll
            for (int hd = 0; hd < 2; hd++)
#pragma unroll
                for (int j = 0; j < 4; j++)
                    upk2(rowlo[hd][j], rowhi[hd][j], kvp[hf][i2][hd][j]);
            float kslo, kshi;
            upk2(kslo, kshi, ksp[hf][i2]);

            int flo = hf * 128 + fg * 4 + 2 * i2;
#pragma unroll
            for (int hd = 0; hd < 2; hd++) {
                int d = hd * 32 + dg * 4;
                *(float4*)(pkv + flo * DDIM + d) =
                    make_float4(rowlo[hd][0], rowlo[hd][1], rowlo[hd][2], rowlo[hd][3]);
                *(float4*)(pkv + (flo + 1) * DDIM + d) =
                    make_float4(rowhi[hd][0], rowhi[hd][1], rowhi[hd][2], rowhi[hd][3]);
            }
            if (dg == 0) { pks[flo] = kslo; pks[flo + 1] = kshi; }
        }
}

// ---------------------------------------------------------------------------
// Reduce (float4-vectorized): sum NSPLIT partials; add 1e-6 to ksum.
// ---------------------------------------------------------------------------
__global__ void favor_reduce_kernel()
{
    int idx4 = blockIdx.x * blockDim.x + threadIdx.x;   // over BHN*FDIM*DDIM/4
    if (idx4 < BHN * FDIM * DDIM / 4) {
        int bh = idx4 / (FDIM * DDIM / 4), r4 = idx4 % (FDIM * DDIM / 4);
        const float4* base = (const float4*)g_part_kv;
        float4 s = make_float4(0.f, 0.f, 0.f, 0.f);
#pragma unroll 8
        for (int sp = 0; sp < NSPLIT; sp++) {
            float4 v = base[((size_t)(bh * NSPLIT + sp)) * (FDIM * DDIM / 4) + r4];
            s.x += v.x; s.y += v.y; s.z += v.z; s.w += v.w;
        }
        ((float4*)g_kv)[idx4] = s;
    }
    if (idx4 < BHN * FDIM) {
        int bh = idx4 / FDIM, f = idx4 % FDIM;
        float s = 0.f;
#pragma unroll 8
        for (int sp = 0; sp < NSPLIT; sp++)
            s += g_part_ks[(bh * NSPLIT + sp) * FDIM + f];
        g_ks[bh * FDIM + f] = s + 1e-6f;
    }
}

// ---------------------------------------------------------------------------
// Kernel B: q-side + output. 512 threads (16 warps), 1 CTA/SM.
// smem = P(64K) + KVT 64x260 (65K) + XsT 64x68 (17K) + E 64x256 (64K)
//        + KSe(1K) + Dnm = 216320 B
// KVT is kv transposed [d][f] (pad 260) so GEMM3 b-operands load as packed
// f-pairs (ulonglong2) -> all-FFMA2 GEMM3 with zero dup/pk MOVs.
// ---------------------------------------------------------------------------
__global__ __launch_bounds__(TBLKB, 1)
void favor_q_kernel(const float* __restrict__ Q, const float* __restrict__ P,
                    float* __restrict__ Out)
{
    extern __shared__ float sm[];
    float* Ps  = sm;                       // [64][256]
    float* KVT = Ps + DDIM * FDIM;         // [64][KVP]
    float* XsT = KVT + DDIM * KVP;         // [64][XPADB]
    float* Es  = XsT + DDIM * XPADB;       // [64][256]
    float* KSe = Es + CHKB * FDIM;         // [256]
    float* Dnm = KSe + FDIM;               // [64]

    const int tid = threadIdx.x;
    const int split = blockIdx.x, bh = blockIdx.y;
    const float* qb = Q + (size_t)bh * NSEQ * DDIM;
    float* ob = Out + (size_t)bh * NSEQ * DDIM;

    {
        const float4* src = (const float4*)P;
        float4* dst = (float4*)Ps;
#pragma unroll
        for (int it = 0; it < (DDIM * FDIM / 4) / TBLKB; it++)
            dst[tid + it * TBLKB] = src[tid + it * TBLKB];
        // kv transposed into KVT[d][f]
        const float* kvsrc = g_kv + (size_t)bh * FDIM * DDIM;
#pragma unroll
        for (int it = 0; it < (FDIM * DDIM) / TBLKB; it++) {
            int idx = tid + it * TBLKB;
            int f = idx >> 6, d = idx & 63;       // coalesced global read
            KVT[d * KVP + f] = kvsrc[idx];
        }
        if (tid < FDIM) KSe[tid] = g_ks[bh * FDIM + tid];   // includes +1e-6
    }

    const int rg = tid >> 5, cg = tid & 31;   // rg 0..15 -> rows rg*4..+3 (64 rows)
    const int w = rg, lane = cg;

    for (int c = 0; c < NCHB; c++) {
        const int n0 = split * RPB + c * CHKB;
        __syncthreads();
#pragma unroll
        for (int it = 0; it < (CHKB * DDIM) / TBLKB; it++) {
            int idx = tid + it * TBLKB;
            int r = idx >> 6, d = idx & 63;
            XsT[d * XPADB + r] = qb[(size_t)(n0 + r) * DDIM + d];
        }
        __syncthreads();

        u64 accp[4][2][2];
        proj_gemm4(XsT, Ps, rg, cg, XPADB, accp);
        float acc[4][2][4];
        unpack4(accp, acc);
        maxexp4(acc);

        // denom[r] = sum_f E[r][f] * kse[f] (GEMM1 epilogue)
        {
            float4 K0 = *(const float4*)(KSe + cg * 4);
            float4 K1 = *(const float4*)(KSe + 128 + cg * 4);
            float k0[4] = {K0.x, K0.y, K0.z, K0.w};
            float k1[4] = {K1.x, K1.y, K1.z, K1.w};
#pragma unroll
            for (int i = 0; i < 4; i++) {
                float dn = 0.f;
#pragma unroll
                for (int j = 0; j < 4; j++)
                    dn += acc[i][0][j] * k0[j] + acc[i][1][j] * k1[j];
#pragma unroll
                for (int off = 16; off > 0; off >>= 1)
                    dn += __shfl_xor_sync(0xffffffffu, dn, off);
                if (cg == 0) Dnm[rg * 4 + i] = dn;
            }
        }
        store_E4(Es, rg, cg, acc);
        __syncthreads();

        // GEMM3 (all-packed): out[r][d] = sum_f E[r][f]*kv[f][d].
        // Warp w owns rows w*4..w*4+3; lane covers d = {lane, 32+lane}.
        // Lanes hold f-even/f-odd partials, combined at the end.
        u64 oap[4][2];
#pragma unroll
        for (int i = 0; i < 4; i++) { oap[i][0] = 0ull; oap[i][1] = 0ull; }
#pragma unroll 4
        for (int f0 = 0; f0 < FDIM; f0 += 4) {
            u64 ap[4][2];
#pragma unroll
            for (int i = 0; i < 4; i++) {
                ulonglong2 A = *(const ulonglong2*)(Es + (w * 4 + i) * FDIM + f0);
                ap[i][0] = A.x; ap[i][1] = A.y;
            }
            ulonglong2 B0 = *(const ulonglong2*)(KVT + lane * KVP + f0);
            ulonglong2 B1 = *(const ulonglong2*)(KVT + (32 + lane) * KVP + f0);
            u64 bp0[2] = {B0.x, B0.y};
            u64 bp1[2] = {B1.x, B1.y};
#pragma unroll
            for (int i = 0; i < 4; i++)
#pragma unroll
                for (int u2 = 0; u2 < 2; u2++) {
                    ffma2(oap[i][0], ap[i][u2], bp0[u2]);
                    ffma2(oap[i][1], ap[i][u2], bp1[u2]);
                }
        }
#pragma unroll
        for (int i = 0; i < 4; i++) {
            float lo0, hi0, lo1, hi1;
            upk2(lo0, hi0, oap[i][0]);
            upk2(lo1, hi1, oap[i][1]);
            float rz = 1.0f / Dnm[w * 4 + i];
            size_t r = (size_t)(n0 + w * 4 + i) * DDIM;
            ob[r + lane]      = (lo0 + hi0) * rz;
            ob[r + 32 + lane] = (lo1 + hi1) * rz;
        }
    }
}

// ---------------------------------------------------------------------------
extern "C" void kernel_launch(void* const* d_in, const int* in_sizes, int n_in,
                              void* d_out, int out_size)
{
    const float* q = (const float*)d_in[0];
    const float* k = (const float*)d_in[1];
    const float* v = (const float*)d_in[2];
    const float* P = (const float*)d_in[3];
    float* out = (float*)d_out;

    const int A_SMEM = (DDIM * FDIM + DDIM * XPADA + CHKA * FDIM + CHKA * DDIM) * 4;        // 115712
    const int B_SMEM = (DDIM * FDIM + DDIM * KVP + DDIM * XPADB + CHKB * FDIM + FDIM + 64) * 4; // 216320

    cudaFuncSetAttribute(favor_k_kernel, cudaFuncAttributeMaxDynamicSharedMemorySize, A_SMEM);
    cudaFuncSetAttribute(favor_q_kernel, cudaFuncAttributeMaxDynamicSharedMemorySize, B_SMEM);

    dim3 grid(NSPLIT, BHN);
    favor_k_kernel<<<grid, TBLKA, A_SMEM>>>(k, v, P);
    favor_reduce_kernel<<<(BHN * FDIM * DDIM / 4 + 255) / 256, 256>>>();
    favor_q_kernel<<<grid, TBLKB, B_SMEM>>>(q, P, out);
}